// round 10
// baseline (speedup 1.0000x reference)
#include <cuda_runtime.h>
#include <cuda_fp16.h>
#include <math.h>
#include <stdint.h>

#define NB 4
#define LL 8192
#define DD 256
#define HH 8
#define DHD 32
#define MROWS (NB * LL)   // 32768
#define KSPLIT 32

typedef unsigned short ush;

// ---------------- scratch (static device globals) --------------------------
__device__ float g_KV   [NB * HH * DHD * DHD];
__device__ float g_Ksum [NB * HH * DHD];
__device__ float g_KVp  [NB * HH * KSPLIT * DHD * DHD];
__device__ float g_Ksp  [NB * HH * KSPLIT * DHD];
// fp16 operands
__device__ ush g_xh [MROWS * DD];
__device__ ush g_sh [MROWS * DD];
__device__ ush g_qf [MROWS * DD];          // Q features
__device__ ush g_kvf[MROWS * 2 * DD];      // [row][0:256]=K feat, [256:512]=V feat
__device__ ush g_ath[MROWS * DD];
__device__ ush g_mh [MROWS * DD];
__device__ ush g_hbh[MROWS * 2 * DD];
// transposed fp16 weights [N][K]
__device__ ush g_Bqh [DD * DD];
__device__ ush g_Bkvh[2 * DD * DD];        // rows 0-255 = Wk cols, 256-511 = Wv cols
__device__ ush g_Bmh [DD * DD];
__device__ ush g_B1h [2 * DD * 2 * DD];
__device__ ush g_B2h [2 * DD * DD];

// ---------------- helpers --------------------------------------------------
__device__ __forceinline__ uint32_t smem_u32(const void* p) {
    uint32_t a;
    asm("{ .reg .u64 t; cvta.to.shared.u64 t, %1; cvt.u32.u64 %0, t; }" : "=r"(a) : "l"(p));
    return a;
}
__device__ __forceinline__ void cp16(uint32_t dst, const void* src) {
    asm volatile("cp.async.cg.shared.global [%0], [%1], 16;" :: "r"(dst), "l"(src) : "memory");
}
__device__ __forceinline__ void ldsm4(uint32_t* r, uint32_t addr) {
    asm volatile("ldmatrix.sync.aligned.m8n8.x4.shared.b16 {%0,%1,%2,%3}, [%4];"
                 : "=r"(r[0]), "=r"(r[1]), "=r"(r[2]), "=r"(r[3]) : "r"(addr));
}
__device__ __forceinline__ void mma16816(float* c, const uint32_t* a, uint32_t b0, uint32_t b1) {
    asm volatile(
        "mma.sync.aligned.m16n8k16.row.col.f32.f16.f16.f32 "
        "{%0,%1,%2,%3}, {%4,%5,%6,%7}, {%8,%9}, {%0,%1,%2,%3};"
        : "+f"(c[0]), "+f"(c[1]), "+f"(c[2]), "+f"(c[3])
        : "r"(a[0]), "r"(a[1]), "r"(a[2]), "r"(a[3]), "r"(b0), "r"(b1));
}
__device__ __forceinline__ ush f2h(float v) {
    return __half_as_ushort(__float2half_rn(v));
}

// 128B rows, 8 x 16B chunks, xor-swizzled
__device__ __forceinline__ uint32_t swz128(int r, int c) {
    return (uint32_t)(r * 128 + ((c ^ (r & 7)) << 4));
}

// ---------------- cp.async pipelined fp16 GEMM -----------------------------
// Tile: 128 x BN. BN=128 -> 256 thr / occ 2 / double-buffered frags;
//                 BN=256 -> 512 thr / occ 1 / single-buffered (reg cap)
// EPI: 0 none, 1 elu+1, 2 leaky, 3 LN(g,b), 4 LN + residual,
//      5 KV-merged (elu+1 iff bcol<256)
template <int EPI, bool CONCAT, bool OUTH, int BN>
__global__ __launch_bounds__(BN == 128 ? 256 : 512, BN == 128 ? 2 : 1)
void gemm_cp(const ush* __restrict__ Ah, const ush* __restrict__ A2h,
             const ush* __restrict__ Bh,
             float* __restrict__ Cf, ush* __restrict__ Ch,
             int kTot, int nFull,
             const float* __restrict__ g, const float* __restrict__ b,
             const float* __restrict__ xres) {
    constexpr int THREADS = (BN == 128) ? 256 : 512;
    constexpr bool DBUF = (BN == 128);
    constexpr int STG = 16384 + BN * 128;
    constexpr int OFF_B = 16384;
    constexpr int STAGE_F = BN + 4;
    constexpr int A_IT = 1024 / THREADS;
    constexpr int B_IT = BN * 8 / THREADS;

    extern __shared__ char smem[];
    const uint32_t sb = smem_u32(smem);
    const int t = threadIdx.x, lane = t & 31, wid = t >> 5;
    const int wm = wid & 3, wn = wid >> 2;
    const int mrow0 = blockIdx.x * 128;
    const int bcol = blockIdx.y * BN;
    const int NC = kTot >> 6;
    const int aStride = CONCAT ? 256 : kTot;

    float acc[2][8][4];
#pragma unroll
    for (int i = 0; i < 2; i++)
#pragma unroll
        for (int j = 0; j < 8; j++)
#pragma unroll
            for (int q = 0; q < 4; q++) acc[i][j][q] = 0.f;

#define ISSUE(icv)                                                               \
    {                                                                            \
        const int _ic = (icv);                                                   \
        if (_ic < NC) {                                                          \
            const int k0 = _ic * 64;                                             \
            const uint32_t base = sb + (_ic % 3) * STG;                          \
            const ush* pah;                                                      \
            int ka = k0;                                                         \
            if (CONCAT && k0 >= 256) { pah = A2h; ka = k0 - 256; }               \
            else { pah = Ah; }                                                   \
            _Pragma("unroll")                                                    \
            for (int _i = 0; _i < A_IT; _i++) {                                  \
                const int idx = t + _i * THREADS;                                \
                const int r = idx >> 3, c = idx & 7;                             \
                cp16(base + swz128(r, c),                                        \
                     pah + (size_t)(mrow0 + r) * aStride + ka + c * 8);          \
            }                                                                    \
            _Pragma("unroll")                                                    \
            for (int _i = 0; _i < B_IT; _i++) {                                  \
                const int idx = t + _i * THREADS;                                \
                const int rb = idx >> 3, cb = idx & 7;                           \
                cp16(base + OFF_B + swz128(rb, cb),                              \
                     Bh + (size_t)(bcol + rb) * kTot + k0 + cb * 8);             \
            }                                                                    \
        }                                                                        \
        asm volatile("cp.async.commit_group;" ::: "memory");                     \
    }

#define LDF(ksv, AF, BF)                                                         \
    {                                                                            \
        const int _ks = (ksv);                                                   \
        _Pragma("unroll")                                                        \
        for (int _i = 0; _i < 2; _i++)                                           \
            ldsm4((AF)[_i], sA32 + swz128(wm * 32 + _i * 16 + lr, _ks * 2 + lh)); \
        _Pragma("unroll")                                                        \
        for (int _j = 0; _j < 4; _j++)                                           \
            ldsm4((BF)[_j], sB32 + swz128(wn * 64 + _j * 16 + lr, _ks * 2 + lh)); \
    }

#define DOMMA(AF, BF)                                                            \
    _Pragma("unroll")                                                            \
    for (int _i = 0; _i < 2; _i++)                                               \
        _Pragma("unroll")                                                        \
        for (int _j2 = 0; _j2 < 4; _j2++) {                                      \
            mma16816(acc[_i][2 * _j2 + 0], (AF)[_i], (BF)[_j2][0], (BF)[_j2][2]); \
            mma16816(acc[_i][2 * _j2 + 1], (AF)[_i], (BF)[_j2][1], (BF)[_j2][3]); \
        }

    ISSUE(0);
    ISSUE(1);

    const int lr = lane & 15, lh = lane >> 4;
    for (int ic = 0; ic < NC; ic++) {
        asm volatile("cp.async.wait_group 1;" ::: "memory");
        __syncthreads();
        ISSUE(ic + 2);
        const uint32_t sA32 = sb + (ic % 3) * STG;
        const uint32_t sB32 = sA32 + OFF_B;
        if (DBUF) {
            uint32_t AF[2][2][4], BF[2][4][4];
            LDF(0, AF[0], BF[0]);
#pragma unroll
            for (int ks = 0; ks < 4; ks++) {
                const int cur = ks & 1;
                if (ks < 3) LDF(ks + 1, AF[cur ^ 1], BF[cur ^ 1]);
                DOMMA(AF[cur], BF[cur]);
            }
        } else {
            uint32_t AF[2][4], BF[4][4];
#pragma unroll
            for (int ks = 0; ks < 4; ks++) {
                LDF(ks, AF, BF);
                DOMMA(AF, BF);
            }
        }
        __syncthreads();
    }
#undef ISSUE
#undef LDF
#undef DOMMA

    // ---- epilogue: frags -> smem staging (coalesced stores) ----
    float* stage = (float*)smem;
    {
        const int lr4 = lane >> 2, lc = (lane & 3) * 2;
#pragma unroll
        for (int i = 0; i < 2; i++) {
            const int r = wm * 32 + i * 16 + lr4;
#pragma unroll
            for (int j = 0; j < 8; j++) {
                const int c = wn * 64 + j * 8 + lc;
                *(float2*)&stage[r * STAGE_F + c] = make_float2(acc[i][j][0], acc[i][j][1]);
                *(float2*)&stage[(r + 8) * STAGE_F + c] = make_float2(acc[i][j][2], acc[i][j][3]);
            }
        }
    }
    __syncthreads();

    float* meanA = (float*)(smem + 128 * STAGE_F * 4);
    float* rstdA = meanA + 128;
    if (EPI >= 3 && EPI != 5) {
        if (t < 128) {
            float s1 = 0.f, s2 = 0.f;
#pragma unroll 8
            for (int c = 0; c < 256; c += 4) {
                float4 v = *(float4*)(stage + t * STAGE_F + c);
                s1 += v.x + v.y + v.z + v.w;
                s2 += v.x * v.x + v.y * v.y + v.z * v.z + v.w * v.w;
            }
            const float m = s1 * (1.f / 256.f);
            const float var = s2 * (1.f / 256.f) - m * m;
            meanA[t] = m;
            rstdA[t] = rsqrtf(var + 1e-5f);
        }
        __syncthreads();
    }

    const bool doElu = (EPI == 1) || (EPI == 5 && bcol < 256);
#pragma unroll 4
    for (int q = 0; q < 16; q++) {
        const int f = q * THREADS + t;
        const int r = f / (BN / 4), c = (f % (BN / 4)) * 4;
        float4 v = *(float4*)(stage + r * STAGE_F + c);
        if (EPI == 1 || EPI == 5) {
            if (doElu) {
                v.x = v.x > 0.f ? v.x + 1.f : expf(v.x);
                v.y = v.y > 0.f ? v.y + 1.f : expf(v.y);
                v.z = v.z > 0.f ? v.z + 1.f : expf(v.z);
                v.w = v.w > 0.f ? v.w + 1.f : expf(v.w);
            }
        } else if (EPI == 2) {
            v.x = v.x >= 0.f ? v.x : 0.1f * v.x;
            v.y = v.y >= 0.f ? v.y : 0.1f * v.y;
            v.z = v.z >= 0.f ? v.z : 0.1f * v.z;
            v.w = v.w >= 0.f ? v.w : 0.1f * v.w;
        } else if (EPI >= 3) {
            const float m = meanA[r], rs = rstdA[r];
            float4 gv = *(const float4*)(g + bcol + c);
            float4 bv = *(const float4*)(b + bcol + c);
            v.x = (v.x - m) * rs * gv.x + bv.x;
            v.y = (v.y - m) * rs * gv.y + bv.y;
            v.z = (v.z - m) * rs * gv.z + bv.z;
            v.w = (v.w - m) * rs * gv.w + bv.w;
            if (EPI == 4) {
                float4 xr = *(const float4*)(xres + (size_t)(mrow0 + r) * 256 + c);
                v.x += xr.x; v.y += xr.y; v.z += xr.z; v.w += xr.w;
            }
        }
        if (OUTH) {
            const size_t o = (size_t)(mrow0 + r) * nFull + bcol + c;
            *(ushort4*)(Ch + o) = make_ushort4(f2h(v.x), f2h(v.y), f2h(v.z), f2h(v.w));
        } else {
            *(float4*)(Cf + (size_t)(mrow0 + r) * nFull + bcol + c) = v;
        }
    }
}

#define SMEM128 98304
#define SMEM256 147456

// ---------------- merged conversion kernels --------------------------------
__global__ __launch_bounds__(256)
void conv_h2(const float* __restrict__ x, const float* __restrict__ s,
             ush* __restrict__ xh, ush* __restrict__ sh, int n4) {
    const int i = blockIdx.x * 256 + threadIdx.x;
    const float* in = blockIdx.y ? s : x;
    ush* outp = blockIdx.y ? sh : xh;
    if (i < n4) {
        float4 v = ((const float4*)in)[i];
        ((ushort4*)outp)[i] = make_ushort4(f2h(v.x), f2h(v.y), f2h(v.z), f2h(v.w));
    }
}

__global__ __launch_bounds__(256)
void conv_w_all(const float* Wq, const float* Wk, const float* Wv,
                const float* Wm, const float* W1, const float* W2,
                ush* Bq, ush* Bkv, ush* Bm, ush* B1, ush* B2) {
    const float* W; ush* B; int K, N;
    switch (blockIdx.z) {
        case 0: W = Wq; B = Bq; K = DD; N = DD; break;
        case 1: W = Wk; B = Bkv; K = DD; N = DD; break;
        case 2: W = Wv; B = Bkv + DD * DD; K = DD; N = DD; break;
        case 3: W = Wm; B = Bm; K = DD; N = DD; break;
        case 4: W = W1; B = B1; K = 2 * DD; N = 2 * DD; break;
        default: W = W2; B = B2; K = 2 * DD; N = DD; break;
    }
    if ((int)blockIdx.x >= N / 32 || (int)blockIdx.y >= K / 32) return;
    __shared__ float tile[32][33];
    const int n0 = blockIdx.x * 32, k0 = blockIdx.y * 32;
    const int tx = threadIdx.x & 31, ty = threadIdx.x >> 5;
#pragma unroll
    for (int j = 0; j < 4; j++)
        tile[ty * 4 + j][tx] = W[(size_t)(k0 + ty * 4 + j) * N + n0 + tx];
    __syncthreads();
#pragma unroll
    for (int j = 0; j < 4; j++) {
        const int nl = ty * 4 + j;
        B[(size_t)(n0 + nl) * K + k0 + tx] = f2h(tile[tx][nl]);
    }
}

// ---------------- KV partial (reads merged fp16 features) ------------------
__global__ __launch_bounds__(256)
void kv_part() {
    const int n = blockIdx.x, h = blockIdx.y, z = blockIdx.z;
    const ush* Kf = g_kvf + (size_t)n * LL * 512 + h * DHD;
    const ush* Vf = g_kvf + (size_t)n * LL * 512 + 256 + h * DHD;
    __shared__ float sh[4096];
    float* Ks = sh;
    float* Vs = sh + 2048;
    const int tid = threadIdx.x;
    const int sp = tid >> 6;
    const int rem = tid & 63;
    const int d0 = (rem >> 3) * 4;
    const int v0 = (rem & 7) * 4;
    float acc[4][4];
    float ksm[4] = {0.f, 0.f, 0.f, 0.f};
#pragma unroll
    for (int i = 0; i < 4; i++)
#pragma unroll
        for (int j = 0; j < 4; j++) acc[i][j] = 0.f;

    const int lr = tid >> 2, lc8 = (tid & 3) * 8;
    const int s_beg = z * (LL / KSPLIT);
    for (int s0 = s_beg; s0 < s_beg + (LL / KSPLIT); s0 += 64) {
        {
            uint4 uk = *(const uint4*)&Kf[(size_t)(s0 + lr) * 512 + lc8];
            uint4 uv = *(const uint4*)&Vf[(size_t)(s0 + lr) * 512 + lc8];
            const __half2* hk = (const __half2*)&uk;
            const __half2* hv = (const __half2*)&uv;
#pragma unroll
            for (int j = 0; j < 4; j++) {
                float2 fk = __half22float2(hk[j]);
                float2 fv = __half22float2(hv[j]);
                Ks[lr * 32 + lc8 + 2 * j + 0] = fk.x;
                Ks[lr * 32 + lc8 + 2 * j + 1] = fk.y;
                Vs[lr * 32 + lc8 + 2 * j + 0] = fv.x;
                Vs[lr * 32 + lc8 + 2 * j + 1] = fv.y;
            }
        }
        __syncthreads();
#pragma unroll 4
        for (int s = sp; s < 64; s += 4) {
            float4 vv = *(const float4*)&Vs[s * 32 + v0];
#pragma unroll
            for (int i = 0; i < 4; i++) {
                const float kk = Ks[s * 32 + d0 + i];
                acc[i][0] += kk * vv.x;
                acc[i][1] += kk * vv.y;
                acc[i][2] += kk * vv.z;
                acc[i][3] += kk * vv.w;
                ksm[i] += kk;
            }
        }
        __syncthreads();
    }
    float* red = sh;
#pragma unroll
    for (int i = 0; i < 4; i++)
#pragma unroll
        for (int j = 0; j < 4; j++) red[tid * 16 + i * 4 + j] = acc[i][j];
    __syncthreads();
    const int p = (n * HH + h) * KSPLIT + z;
    if (sp == 0) {
        float* outp = g_KVp + (size_t)p * 1024;
#pragma unroll
        for (int i = 0; i < 4; i++)
#pragma unroll
            for (int j = 0; j < 4; j++) {
                float s = red[rem * 16 + i * 4 + j] + red[(64 + rem) * 16 + i * 4 + j]
                        + red[(128 + rem) * 16 + i * 4 + j] + red[(192 + rem) * 16 + i * 4 + j];
                outp[(d0 + i) * 32 + v0 + j] = s;
            }
    }
    __syncthreads();
#pragma unroll
    for (int i = 0; i < 4; i++) red[tid * 4 + i] = ksm[i];
    __syncthreads();
    if (sp == 0 && (rem & 7) == 0) {
#pragma unroll
        for (int i = 0; i < 4; i++) {
            float s = red[rem * 4 + i] + red[(64 + rem) * 4 + i]
                    + red[(128 + rem) * 4 + i] + red[(192 + rem) * 4 + i];
            g_Ksp[(size_t)p * 32 + d0 + i] = s;
        }
    }
}

__global__ __launch_bounds__(256)
void kv_reduce() {
    const int bh = blockIdx.x;
    for (int idx = threadIdx.x; idx < 1024; idx += 256) {
        float s = 0.f;
#pragma unroll 8
        for (int z = 0; z < KSPLIT; z++)
            s += g_KVp[((size_t)bh * KSPLIT + z) * 1024 + idx];
        g_KV[(size_t)bh * 1024 + idx] = s;
    }
    if (threadIdx.x < 32) {
        float s = 0.f;
#pragma unroll 8
        for (int z = 0; z < KSPLIT; z++)
            s += g_Ksp[((size_t)bh * KSPLIT + z) * 32 + threadIdx.x];
        g_Ksum[bh * 32 + threadIdx.x] = s;
    }
}

// ---------------- per-token message (16 tokens/block) ----------------------
__global__ __launch_bounds__(256)
void attn_kernel() {
    __shared__ float KVs[HH * DHD * DHD];
    __shared__ float Kss[HH * DHD];
    const int tid = threadIdx.x;
    const int tok0 = blockIdx.x * 16;
    const int n = tok0 / LL;
    const float* KVg = g_KV + (size_t)n * HH * DHD * DHD;
    for (int i = tid; i < HH * DHD * DHD; i += 256) KVs[i] = KVg[i];
    for (int i = tid; i < HH * DHD; i += 256) Kss[i] = g_Ksum[(size_t)n * HH * DHD + i];
    __syncthreads();

    const int warp = tid >> 5, lane = tid & 31;
#pragma unroll
    for (int rep = 0; rep < 2; rep++) {
        const int tok = tok0 + warp + rep * 8;
        const ush* Q = g_qf + (size_t)tok * DD;
        float q[HH];
#pragma unroll
        for (int h = 0; h < HH; h++)
            q[h] = __half2float(__ushort_as_half(Q[h * DHD + lane]));
#pragma unroll
        for (int h = 0; h < HH; h++) {
            float p = q[h] * Kss[h * DHD + lane];
#pragma unroll
            for (int o = 16; o > 0; o >>= 1) p += __shfl_xor_sync(0xffffffffu, p, o);
            const float z = 1.f / (p + 1e-6f);
            float acc = 0.f;
#pragma unroll
            for (int dd = 0; dd < DHD; dd++)
                acc += __shfl_sync(0xffffffffu, q[h], dd) * KVs[h * DHD * DHD + dd * DHD + lane];
            g_ath[(size_t)tok * DD + h * DHD + lane] = f2h(acc * z);
        }
    }
}

// ---------------- launch ---------------------------------------------------
extern "C" void kernel_launch(void* const* d_in, const int* in_sizes, int n_in,
                              void* d_out, int out_size) {
    const float* x   = (const float*)d_in[0];
    const float* src = (const float*)d_in[1];
    const float* Wq  = (const float*)d_in[2];
    const float* Wk  = (const float*)d_in[3];
    const float* Wv  = (const float*)d_in[4];
    const float* Wm  = (const float*)d_in[5];
    const float* W1  = (const float*)d_in[6];
    const float* W2  = (const float*)d_in[7];
    const float* g1  = (const float*)d_in[8];
    const float* b1  = (const float*)d_in[9];
    const float* g2  = (const float*)d_in[10];
    const float* b2  = (const float*)d_in[11];
    float* out = (float*)d_out;

    ush *xh, *sh_, *qf, *kvf, *ath, *mh, *hbh;
    cudaGetSymbolAddress((void**)&xh, g_xh);
    cudaGetSymbolAddress((void**)&sh_, g_sh);
    cudaGetSymbolAddress((void**)&qf, g_qf);
    cudaGetSymbolAddress((void**)&kvf, g_kvf);
    cudaGetSymbolAddress((void**)&ath, g_ath);
    cudaGetSymbolAddress((void**)&mh, g_mh);
    cudaGetSymbolAddress((void**)&hbh, g_hbh);
    ush *Bqh, *Bkvh, *Bmh, *B1h, *B2h;
    cudaGetSymbolAddress((void**)&Bqh, g_Bqh);
    cudaGetSymbolAddress((void**)&Bkvh, g_Bkvh);
    cudaGetSymbolAddress((void**)&Bmh, g_Bmh);
    cudaGetSymbolAddress((void**)&B1h, g_B1h);
    cudaGetSymbolAddress((void**)&B2h, g_B2h);

    cudaFuncSetAttribute(gemm_cp<1, false, true, 128>,  cudaFuncAttributeMaxDynamicSharedMemorySize, SMEM128);
    cudaFuncSetAttribute(gemm_cp<5, false, true, 128>,  cudaFuncAttributeMaxDynamicSharedMemorySize, SMEM128);
    cudaFuncSetAttribute(gemm_cp<2, true, true, 128>,   cudaFuncAttributeMaxDynamicSharedMemorySize, SMEM128);
    cudaFuncSetAttribute(gemm_cp<3, false, true, 256>,  cudaFuncAttributeMaxDynamicSharedMemorySize, SMEM256);
    cudaFuncSetAttribute(gemm_cp<4, false, false, 256>, cudaFuncAttributeMaxDynamicSharedMemorySize, SMEM256);

    const int n4 = MROWS * DD / 4;
    conv_h2<<<dim3((n4 + 255) / 256, 2), 256>>>(x, src, xh, sh_, n4);
    conv_w_all<<<dim3(16, 16, 6), 256>>>(Wq, Wk, Wv, Wm, W1, W2,
                                         Bqh, Bkvh, Bmh, B1h, B2h);

    const dim3 gQ(MROWS / 128, 2);     // N=256, BN=128
    const dim3 gKV(MROWS / 128, 4);    // N=512, BN=128
    const dim3 gW1(MROWS / 128, 4);    // N=512, BN=128
    const dim3 gLN(MROWS / 128, 1);    // N=256, BN=256

    // Q features (elu+1)
    gemm_cp<1, false, true, 128><<<gQ, 256, SMEM128>>>(xh, nullptr, Bqh,
        nullptr, qf, 256, 256, nullptr, nullptr, nullptr);
    // K+V merged (elu+1 on cols<256)
    gemm_cp<5, false, true, 128><<<gKV, 256, SMEM128>>>(sh_, nullptr, Bkvh,
        nullptr, kvf, 256, 512, nullptr, nullptr, nullptr);

    kv_part<<<dim3(NB, HH, KSPLIT), 256>>>();
    kv_reduce<<<NB * HH, 256>>>();
    attn_kernel<<<MROWS / 16, 256>>>();

    // merge heads + fused LN1 -> fp16
    gemm_cp<3, false, true, 256><<<gLN, 512, SMEM256>>>(ath, nullptr, Bmh,
        nullptr, mh, 256, 256, g1, b1, nullptr);
    // concat -> W1 (leaky) -> fp16
    gemm_cp<2, true, true, 128><<<gW1, 256, SMEM128>>>(xh, mh, B1h,
        nullptr, hbh, 512, 512, nullptr, nullptr, nullptr);
    // W2 + fused LN2 + residual -> out (fp32)
    gemm_cp<4, false, false, 256><<<gLN, 512, SMEM256>>>(hbh, nullptr, B2h,
        out, nullptr, 512, 256, g2, b2, x);
}

// round 11
// speedup vs baseline: 1.0715x; 1.0715x over previous
#include <cuda_runtime.h>
#include <cuda_fp16.h>
#include <math.h>
#include <stdint.h>

#define NB 4
#define LL 8192
#define DD 256
#define HH 8
#define DHD 32
#define MROWS (NB * LL)   // 32768
#define KSPLIT 32

typedef unsigned short ush;

// ---------------- scratch (static device globals) --------------------------
__device__ float g_KV   [NB * HH * DHD * DHD];
__device__ float g_Ksum [NB * HH * DHD];
__device__ float g_KVp  [NB * HH * KSPLIT * DHD * DHD];
__device__ float g_Ksp  [NB * HH * KSPLIT * DHD];
// fp16 operands
__device__ ush g_xh [MROWS * DD];
__device__ ush g_sh [MROWS * DD];
__device__ ush g_qf [MROWS * DD];          // Q features
__device__ ush g_kf [MROWS * DD];          // K features
__device__ ush g_vf [MROWS * DD];          // V features
__device__ ush g_ath[MROWS * DD];
__device__ ush g_mh [MROWS * DD];
__device__ ush g_hbh[MROWS * 2 * DD];
// transposed fp16 weights [N][K]
__device__ ush g_Bqh[DD * DD];
__device__ ush g_Bkh[DD * DD];
__device__ ush g_Bvh[DD * DD];
__device__ ush g_Bmh[DD * DD];
__device__ ush g_B1h[2 * DD * 2 * DD];
__device__ ush g_B2h[2 * DD * DD];

// ---------------- helpers --------------------------------------------------
__device__ __forceinline__ uint32_t smem_u32(const void* p) {
    uint32_t a;
    asm("{ .reg .u64 t; cvta.to.shared.u64 t, %1; cvt.u32.u64 %0, t; }" : "=r"(a) : "l"(p));
    return a;
}
__device__ __forceinline__ void cp16(uint32_t dst, const void* src) {
    asm volatile("cp.async.cg.shared.global [%0], [%1], 16;" :: "r"(dst), "l"(src) : "memory");
}
__device__ __forceinline__ void ldsm4(uint32_t* r, uint32_t addr) {
    asm volatile("ldmatrix.sync.aligned.m8n8.x4.shared.b16 {%0,%1,%2,%3}, [%4];"
                 : "=r"(r[0]), "=r"(r[1]), "=r"(r[2]), "=r"(r[3]) : "r"(addr));
}
__device__ __forceinline__ void mma16816(float* c, const uint32_t* a, uint32_t b0, uint32_t b1) {
    asm volatile(
        "mma.sync.aligned.m16n8k16.row.col.f32.f16.f16.f32 "
        "{%0,%1,%2,%3}, {%4,%5,%6,%7}, {%8,%9}, {%0,%1,%2,%3};"
        : "+f"(c[0]), "+f"(c[1]), "+f"(c[2]), "+f"(c[3])
        : "r"(a[0]), "r"(a[1]), "r"(a[2]), "r"(a[3]), "r"(b0), "r"(b1));
}
__device__ __forceinline__ ush f2h(float v) {
    return __half_as_ushort(__float2half_rn(v));
}

// 128B rows, 8 x 16B chunks, xor-swizzled
__device__ __forceinline__ uint32_t swz128(int r, int c) {
    return (uint32_t)(r * 128 + ((c ^ (r & 7)) << 4));
}

// ---------------- cp.async pipelined fp16 GEMM -----------------------------
// Tile: 128 x BN. BN=128 -> 256 thr / occ 2;  BN=256 -> 512 thr / occ 1 (LN)
// EPI: 0 none, 1 elu+1, 2 leaky, 3 LN(g,b), 4 LN + residual
template <int EPI, bool CONCAT, bool OUTH, int BN>
__global__ __launch_bounds__(BN == 128 ? 256 : 512, BN == 128 ? 2 : 1)
void gemm_cp(const ush* __restrict__ Ah, const ush* __restrict__ A2h,
             const ush* __restrict__ Bh,
             float* __restrict__ Cf, ush* __restrict__ Ch,
             int kTot, int nFull,
             const float* __restrict__ g, const float* __restrict__ b,
             const float* __restrict__ xres) {
    constexpr int THREADS = (BN == 128) ? 256 : 512;
    constexpr int STG = 16384 + BN * 128;
    constexpr int OFF_B = 16384;
    constexpr int STAGE_F = BN + 4;
    constexpr int A_IT = 1024 / THREADS;
    constexpr int B_IT = BN * 8 / THREADS;

    extern __shared__ char smem[];
    const uint32_t sb = smem_u32(smem);
    const int t = threadIdx.x, lane = t & 31, wid = t >> 5;
    const int wm = wid & 3, wn = wid >> 2;
    const int mrow0 = blockIdx.x * 128;
    const int bcol = blockIdx.y * BN;
    const int NC = kTot >> 6;
    const int aStride = CONCAT ? 256 : kTot;

    float acc[2][8][4];
#pragma unroll
    for (int i = 0; i < 2; i++)
#pragma unroll
        for (int j = 0; j < 8; j++)
#pragma unroll
            for (int q = 0; q < 4; q++) acc[i][j][q] = 0.f;

#define ISSUE(icv)                                                               \
    {                                                                            \
        const int _ic = (icv);                                                   \
        if (_ic < NC) {                                                          \
            const int k0 = _ic * 64;                                             \
            const uint32_t base = sb + (_ic % 3) * STG;                          \
            const ush* pah;                                                      \
            int ka = k0;                                                         \
            if (CONCAT && k0 >= 256) { pah = A2h; ka = k0 - 256; }               \
            else { pah = Ah; }                                                   \
            _Pragma("unroll")                                                    \
            for (int _i = 0; _i < A_IT; _i++) {                                  \
                const int idx = t + _i * THREADS;                                \
                const int r = idx >> 3, c = idx & 7;                             \
                cp16(base + swz128(r, c),                                        \
                     pah + (size_t)(mrow0 + r) * aStride + ka + c * 8);          \
            }                                                                    \
            _Pragma("unroll")                                                    \
            for (int _i = 0; _i < B_IT; _i++) {                                  \
                const int idx = t + _i * THREADS;                                \
                const int rb = idx >> 3, cb = idx & 7;                           \
                cp16(base + OFF_B + swz128(rb, cb),                              \
                     Bh + (size_t)(bcol + rb) * kTot + k0 + cb * 8);             \
            }                                                                    \
        }                                                                        \
        asm volatile("cp.async.commit_group;" ::: "memory");                     \
    }

    ISSUE(0);
    ISSUE(1);

    const int lr = lane & 15, lh = lane >> 4;
    for (int ic = 0; ic < NC; ic++) {
        asm volatile("cp.async.wait_group 1;" ::: "memory");
        __syncthreads();   // data of stage ic visible; also fences stage (ic)%3 reuse
        ISSUE(ic + 2);
        const uint32_t sA32 = sb + (ic % 3) * STG;
        const uint32_t sB32 = sA32 + OFF_B;
#pragma unroll
        for (int ks = 0; ks < 4; ks++) {
            uint32_t AF[2][4], Bf[4][4];
#pragma unroll
            for (int i = 0; i < 2; i++) {
                const int r = wm * 32 + i * 16 + lr;
                ldsm4(AF[i], sA32 + swz128(r, ks * 2 + lh));
            }
#pragma unroll
            for (int j2 = 0; j2 < 4; j2++) {
                const int n = wn * 64 + j2 * 16 + lr;
                ldsm4(Bf[j2], sB32 + swz128(n, ks * 2 + lh));
            }
#pragma unroll
            for (int i = 0; i < 2; i++)
#pragma unroll
                for (int j2 = 0; j2 < 4; j2++) {
                    mma16816(acc[i][2 * j2 + 0], AF[i], Bf[j2][0], Bf[j2][2]);
                    mma16816(acc[i][2 * j2 + 1], AF[i], Bf[j2][1], Bf[j2][3]);
                }
        }
        // no trailing barrier: next iteration's leading __syncthreads orders
        // stage reuse; epilogue barrier below orders the smem-stage rewrite.
    }
#undef ISSUE

    __syncthreads();   // all warps done reading operand stages before staging C

    // ---- epilogue: frags -> smem staging ----
    float* stage = (float*)smem;
    {
        const int lr4 = lane >> 2, lc = (lane & 3) * 2;
#pragma unroll
        for (int i = 0; i < 2; i++) {
            const int r = wm * 32 + i * 16 + lr4;
#pragma unroll
            for (int j = 0; j < 8; j++) {
                const int c = wn * 64 + j * 8 + lc;
                *(float2*)&stage[r * STAGE_F + c] = make_float2(acc[i][j][0], acc[i][j][1]);
                *(float2*)&stage[(r + 8) * STAGE_F + c] = make_float2(acc[i][j][2], acc[i][j][3]);
            }
        }
    }
    __syncthreads();

    float* meanA = (float*)(smem + 128 * STAGE_F * 4);
    float* rstdA = meanA + 128;
    if (EPI >= 3) {
        if (t < 128) {
            float s1 = 0.f, s2 = 0.f;
#pragma unroll 8
            for (int c = 0; c < 256; c += 4) {
                float4 v = *(float4*)(stage + t * STAGE_F + c);
                s1 += v.x + v.y + v.z + v.w;
                s2 += v.x * v.x + v.y * v.y + v.z * v.z + v.w * v.w;
            }
            const float m = s1 * (1.f / 256.f);
            const float var = s2 * (1.f / 256.f) - m * m;
            meanA[t] = m;
            rstdA[t] = rsqrtf(var + 1e-5f);
        }
        __syncthreads();
    }

#pragma unroll 4
    for (int q = 0; q < 16; q++) {
        const int f = q * THREADS + t;
        const int r = f / (BN / 4), c = (f % (BN / 4)) * 4;
        float4 v = *(float4*)(stage + r * STAGE_F + c);
        if (EPI == 1) {
            v.x = v.x > 0.f ? v.x + 1.f : expf(v.x);
            v.y = v.y > 0.f ? v.y + 1.f : expf(v.y);
            v.z = v.z > 0.f ? v.z + 1.f : expf(v.z);
            v.w = v.w > 0.f ? v.w + 1.f : expf(v.w);
        } else if (EPI == 2) {
            v.x = v.x >= 0.f ? v.x : 0.1f * v.x;
            v.y = v.y >= 0.f ? v.y : 0.1f * v.y;
            v.z = v.z >= 0.f ? v.z : 0.1f * v.z;
            v.w = v.w >= 0.f ? v.w : 0.1f * v.w;
        } else if (EPI >= 3) {
            const float m = meanA[r], rs = rstdA[r];
            float4 gv = *(const float4*)(g + bcol + c);
            float4 bv = *(const float4*)(b + bcol + c);
            v.x = (v.x - m) * rs * gv.x + bv.x;
            v.y = (v.y - m) * rs * gv.y + bv.y;
            v.z = (v.z - m) * rs * gv.z + bv.z;
            v.w = (v.w - m) * rs * gv.w + bv.w;
            if (EPI == 4) {
                float4 xr = *(const float4*)(xres + (size_t)(mrow0 + r) * 256 + c);
                v.x += xr.x; v.y += xr.y; v.z += xr.z; v.w += xr.w;
            }
        }
        if (OUTH) {
            const size_t o = (size_t)(mrow0 + r) * nFull + bcol + c;
            *(ushort4*)(Ch + o) = make_ushort4(f2h(v.x), f2h(v.y), f2h(v.z), f2h(v.w));
        } else {
            *(float4*)(Cf + (size_t)(mrow0 + r) * nFull + bcol + c) = v;
        }
    }
}

#define SMEM128 98304
#define SMEM256 147456

// ---------------- merged conversion kernels --------------------------------
__global__ __launch_bounds__(256)
void conv_h2(const float* __restrict__ x, const float* __restrict__ s,
             ush* __restrict__ xh, ush* __restrict__ sh, int n4) {
    const int i = blockIdx.x * 256 + threadIdx.x;
    const float* in = blockIdx.y ? s : x;
    ush* outp = blockIdx.y ? sh : xh;
    if (i < n4) {
        float4 v = ((const float4*)in)[i];
        ((ushort4*)outp)[i] = make_ushort4(f2h(v.x), f2h(v.y), f2h(v.z), f2h(v.w));
    }
}

__global__ __launch_bounds__(256)
void conv_w_all(const float* Wq, const float* Wk, const float* Wv,
                const float* Wm, const float* W1, const float* W2,
                ush* Bq, ush* Bk, ush* Bv, ush* Bm, ush* B1, ush* B2) {
    const float* W; ush* B; int K, N;
    switch (blockIdx.z) {
        case 0: W = Wq; B = Bq; K = DD; N = DD; break;
        case 1: W = Wk; B = Bk; K = DD; N = DD; break;
        case 2: W = Wv; B = Bv; K = DD; N = DD; break;
        case 3: W = Wm; B = Bm; K = DD; N = DD; break;
        case 4: W = W1; B = B1; K = 2 * DD; N = 2 * DD; break;
        default: W = W2; B = B2; K = 2 * DD; N = DD; break;
    }
    if ((int)blockIdx.x >= N / 32 || (int)blockIdx.y >= K / 32) return;
    __shared__ float tile[32][33];
    const int n0 = blockIdx.x * 32, k0 = blockIdx.y * 32;
    const int tx = threadIdx.x & 31, ty = threadIdx.x >> 5;
#pragma unroll
    for (int j = 0; j < 4; j++)
        tile[ty * 4 + j][tx] = W[(size_t)(k0 + ty * 4 + j) * N + n0 + tx];
    __syncthreads();
#pragma unroll
    for (int j = 0; j < 4; j++) {
        const int nl = ty * 4 + j;
        B[(size_t)(n0 + nl) * K + k0 + tx] = f2h(tile[tx][nl]);
    }
}

// ---------------- KV partial (fp16 features) --------------------------------
__global__ __launch_bounds__(256)
void kv_part() {
    const int n = blockIdx.x, h = blockIdx.y, z = blockIdx.z;
    const ush* Kf = g_kf + (size_t)n * LL * DD + h * DHD;
    const ush* Vf = g_vf + (size_t)n * LL * DD + h * DHD;
    __shared__ float sh[4096];
    float* Ks = sh;
    float* Vs = sh + 2048;
    const int tid = threadIdx.x;
    const int sp = tid >> 6;
    const int rem = tid & 63;
    const int d0 = (rem >> 3) * 4;
    const int v0 = (rem & 7) * 4;
    float acc[4][4];
    float ksm[4] = {0.f, 0.f, 0.f, 0.f};
#pragma unroll
    for (int i = 0; i < 4; i++)
#pragma unroll
        for (int j = 0; j < 4; j++) acc[i][j] = 0.f;

    const int lr = tid >> 2, lc8 = (tid & 3) * 8;
    const int s_beg = z * (LL / KSPLIT);
    for (int s0 = s_beg; s0 < s_beg + (LL / KSPLIT); s0 += 64) {
        {
            uint4 uk = *(const uint4*)&Kf[(size_t)(s0 + lr) * DD + lc8];
            uint4 uv = *(const uint4*)&Vf[(size_t)(s0 + lr) * DD + lc8];
            const __half2* hk = (const __half2*)&uk;
            const __half2* hv = (const __half2*)&uv;
#pragma unroll
            for (int j = 0; j < 4; j++) {
                float2 fk = __half22float2(hk[j]);
                float2 fv = __half22float2(hv[j]);
                Ks[lr * 32 + lc8 + 2 * j + 0] = fk.x;
                Ks[lr * 32 + lc8 + 2 * j + 1] = fk.y;
                Vs[lr * 32 + lc8 + 2 * j + 0] = fv.x;
                Vs[lr * 32 + lc8 + 2 * j + 1] = fv.y;
            }
        }
        __syncthreads();
#pragma unroll 4
        for (int s = sp; s < 64; s += 4) {
            float4 vv = *(const float4*)&Vs[s * 32 + v0];
#pragma unroll
            for (int i = 0; i < 4; i++) {
                const float kk = Ks[s * 32 + d0 + i];
                acc[i][0] += kk * vv.x;
                acc[i][1] += kk * vv.y;
                acc[i][2] += kk * vv.z;
                acc[i][3] += kk * vv.w;
                ksm[i] += kk;
            }
        }
        __syncthreads();
    }
    float* red = sh;
#pragma unroll
    for (int i = 0; i < 4; i++)
#pragma unroll
        for (int j = 0; j < 4; j++) red[tid * 16 + i * 4 + j] = acc[i][j];
    __syncthreads();
    const int p = (n * HH + h) * KSPLIT + z;
    if (sp == 0) {
        float* outp = g_KVp + (size_t)p * 1024;
#pragma unroll
        for (int i = 0; i < 4; i++)
#pragma unroll
            for (int j = 0; j < 4; j++) {
                float s = red[rem * 16 + i * 4 + j] + red[(64 + rem) * 16 + i * 4 + j]
                        + red[(128 + rem) * 16 + i * 4 + j] + red[(192 + rem) * 16 + i * 4 + j];
                outp[(d0 + i) * 32 + v0 + j] = s;
            }
    }
    __syncthreads();
#pragma unroll
    for (int i = 0; i < 4; i++) red[tid * 4 + i] = ksm[i];
    __syncthreads();
    if (sp == 0 && (rem & 7) == 0) {
#pragma unroll
        for (int i = 0; i < 4; i++) {
            float s = red[rem * 4 + i] + red[(64 + rem) * 4 + i]
                    + red[(128 + rem) * 4 + i] + red[(192 + rem) * 4 + i];
            g_Ksp[(size_t)p * 32 + d0 + i] = s;
        }
    }
}

__global__ __launch_bounds__(256)
void kv_reduce() {
    const int bh = blockIdx.x;
    for (int idx = threadIdx.x; idx < 1024; idx += 256) {
        float s = 0.f;
#pragma unroll 8
        for (int z = 0; z < KSPLIT; z++)
            s += g_KVp[((size_t)bh * KSPLIT + z) * 1024 + idx];
        g_KV[(size_t)bh * 1024 + idx] = s;
    }
    if (threadIdx.x < 32) {
        float s = 0.f;
#pragma unroll 8
        for (int z = 0; z < KSPLIT; z++)
            s += g_Ksp[((size_t)bh * KSPLIT + z) * 32 + threadIdx.x];
        g_Ksum[bh * 32 + threadIdx.x] = s;
    }
}

// ---------------- per-token message (fp16 in / fp16 out) -------------------
__global__ __launch_bounds__(256)
void attn_kernel() {
    __shared__ float KVs[HH * DHD * DHD];
    __shared__ float Kss[HH * DHD];
    const int tid = threadIdx.x;
    const int tok0 = blockIdx.x * 8;
    const int n = tok0 / LL;
    const float* KVg = g_KV + (size_t)n * HH * DHD * DHD;
    for (int i = tid; i < HH * DHD * DHD; i += 256) KVs[i] = KVg[i];
    for (int i = tid; i < HH * DHD; i += 256) Kss[i] = g_Ksum[(size_t)n * HH * DHD + i];
    __syncthreads();

    const int warp = tid >> 5, lane = tid & 31;
    const int tok = tok0 + warp;
    const ush* Q = g_qf + (size_t)tok * DD;
    float q[HH];
#pragma unroll
    for (int h = 0; h < HH; h++)
        q[h] = __half2float(__ushort_as_half(Q[h * DHD + lane]));

#pragma unroll
    for (int h = 0; h < HH; h++) {
        float p = q[h] * Kss[h * DHD + lane];
#pragma unroll
        for (int o = 16; o > 0; o >>= 1) p += __shfl_xor_sync(0xffffffffu, p, o);
        const float z = 1.f / (p + 1e-6f);
        float acc = 0.f;
#pragma unroll
        for (int dd = 0; dd < DHD; dd++)
            acc += __shfl_sync(0xffffffffu, q[h], dd) * KVs[h * DHD * DHD + dd * DHD + lane];
        g_ath[(size_t)tok * DD + h * DHD + lane] = f2h(acc * z);
    }
}

// ---------------- launch ---------------------------------------------------
extern "C" void kernel_launch(void* const* d_in, const int* in_sizes, int n_in,
                              void* d_out, int out_size) {
    const float* x   = (const float*)d_in[0];
    const float* src = (const float*)d_in[1];
    const float* Wq  = (const float*)d_in[2];
    const float* Wk  = (const float*)d_in[3];
    const float* Wv  = (const float*)d_in[4];
    const float* Wm  = (const float*)d_in[5];
    const float* W1  = (const float*)d_in[6];
    const float* W2  = (const float*)d_in[7];
    const float* g1  = (const float*)d_in[8];
    const float* b1  = (const float*)d_in[9];
    const float* g2  = (const float*)d_in[10];
    const float* b2  = (const float*)d_in[11];
    float* out = (float*)d_out;

    ush *xh, *sh_, *qf, *kf, *vf, *ath, *mh, *hbh;
    cudaGetSymbolAddress((void**)&xh, g_xh);
    cudaGetSymbolAddress((void**)&sh_, g_sh);
    cudaGetSymbolAddress((void**)&qf, g_qf);
    cudaGetSymbolAddress((void**)&kf, g_kf);
    cudaGetSymbolAddress((void**)&vf, g_vf);
    cudaGetSymbolAddress((void**)&ath, g_ath);
    cudaGetSymbolAddress((void**)&mh, g_mh);
    cudaGetSymbolAddress((void**)&hbh, g_hbh);
    ush *Bqh, *Bkh, *Bvh, *Bmh, *B1h, *B2h;
    cudaGetSymbolAddress((void**)&Bqh, g_Bqh);
    cudaGetSymbolAddress((void**)&Bkh, g_Bkh);
    cudaGetSymbolAddress((void**)&Bvh, g_Bvh);
    cudaGetSymbolAddress((void**)&Bmh, g_Bmh);
    cudaGetSymbolAddress((void**)&B1h, g_B1h);
    cudaGetSymbolAddress((void**)&B2h, g_B2h);

    cudaFuncSetAttribute(gemm_cp<1, false, true, 128>,  cudaFuncAttributeMaxDynamicSharedMemorySize, SMEM128);
    cudaFuncSetAttribute(gemm_cp<0, false, true, 128>,  cudaFuncAttributeMaxDynamicSharedMemorySize, SMEM128);
    cudaFuncSetAttribute(gemm_cp<2, true, true, 128>,   cudaFuncAttributeMaxDynamicSharedMemorySize, SMEM128);
    cudaFuncSetAttribute(gemm_cp<3, false, true, 256>,  cudaFuncAttributeMaxDynamicSharedMemorySize, SMEM256);
    cudaFuncSetAttribute(gemm_cp<4, false, false, 256>, cudaFuncAttributeMaxDynamicSharedMemorySize, SMEM256);

    const int n4 = MROWS * DD / 4;
    conv_h2<<<dim3((n4 + 255) / 256, 2), 256>>>(x, src, xh, sh_, n4);
    conv_w_all<<<dim3(16, 16, 6), 256>>>(Wq, Wk, Wv, Wm, W1, W2,
                                         Bqh, Bkh, Bvh, Bmh, B1h, B2h);

    const dim3 gQKV(MROWS / 128, 2);   // BN=128
    const dim3 gW1(MROWS / 128, 4);    // BN=128
    const dim3 gLN(MROWS / 128, 1);    // BN=256

    // Q/K/V features -> fp16 (elu+1 for Q,K)
    gemm_cp<1, false, true, 128><<<gQKV, 256, SMEM128>>>(xh, nullptr, Bqh,
        nullptr, qf, 256, 256, nullptr, nullptr, nullptr);
    gemm_cp<1, false, true, 128><<<gQKV, 256, SMEM128>>>(sh_, nullptr, Bkh,
        nullptr, kf, 256, 256, nullptr, nullptr, nullptr);
    gemm_cp<0, false, true, 128><<<gQKV, 256, SMEM128>>>(sh_, nullptr, Bvh,
        nullptr, vf, 256, 256, nullptr, nullptr, nullptr);

    kv_part<<<dim3(NB, HH, KSPLIT), 256>>>();
    kv_reduce<<<NB * HH, 256>>>();
    attn_kernel<<<MROWS / 8, 256>>>();

    // merge heads + fused LN1 -> fp16
    gemm_cp<3, false, true, 256><<<gLN, 512, SMEM256>>>(ath, nullptr, Bmh,
        nullptr, mh, 256, 256, g1, b1, nullptr);
    // concat -> W1 (leaky) -> fp16
    gemm_cp<2, true, true, 128><<<gW1, 256, SMEM128>>>(xh, mh, B1h,
        nullptr, hbh, 512, 512, nullptr, nullptr, nullptr);
    // W2 + fused LN2 + residual -> out (fp32)
    gemm_cp<4, false, false, 256><<<gLN, 512, SMEM256>>>(hbh, nullptr, B2h,
        out, nullptr, 512, 256, g2, b2, x);
}